// round 3
// baseline (speedup 1.0000x reference)
#include <cuda_runtime.h>

#define BB 4
#define HH 256
#define WW 256
#define CC 16

// ---------------------------------------------------------------------------
// Compile-time Batcher odd-even mergesort network for arbitrary n.
// (Arbitrary-length variant of Batcher odd-even mergesort.)
// Marked __host__ __device__ so nvcc accepts the constexpr evaluation in
// device code without --expt-relaxed-constexpr; it is still folded entirely
// at compile time. The comparator loop is fully unrolled so every index is a
// compile-time constant -> pure register code. Since callers read only a
// single rank, DCE prunes every compare-exchange outside that output's
// dependency cone, turning the full sorter into a selection network.
// ---------------------------------------------------------------------------
struct Net {
    int n;
    unsigned char ia[1024];
    unsigned char ib[1024];
};

template <int N>
__host__ __device__ constexpr Net make_net() {
    Net net{};
    for (int p = 1; p < N; p *= 2)
        for (int k = p; k >= 1; k /= 2)
            for (int j = k % p; j <= N - 1 - k; j += 2 * k) {
                int lim = (k - 1 < N - j - k - 1) ? (k - 1) : (N - j - k - 1);
                for (int i = 0; i <= lim; i++)
                    if ((i + j) / (2 * p) == (i + j + k) / (2 * p)) {
                        net.ia[net.n] = (unsigned char)(i + j);
                        net.ib[net.n] = (unsigned char)(i + j + k);
                        net.n = net.n + 1;
                    }
            }
    return net;
}

template <int N, int RANK>
__device__ __forceinline__ float rank_select(float (&v)[N]) {
    constexpr Net net = make_net<N>();
#pragma unroll
    for (int t = 0; t < net.n; t++) {
        const int a = net.ia[t];
        const int b = net.ib[t];
        float x = v[a];
        float y = v[b];
        v[a] = fminf(x, y);
        v[b] = fmaxf(x, y);
    }
    return v[RANK];
}

// ---------------------------------------------------------------------------
// Block: 128 threads = 8 pixels (horizontal run) x 16 channels.
// Each thread gathers its 7x7 zero-padded window (clamped addresses, select
// after load -> branchless, always-valid addresses), runs the three selection
// networks, deposits the 3 features into smem, then the same threads apply
// the 48x16 1x1-conv weights with coalesced output stores.
// ---------------------------------------------------------------------------
__global__ void __launch_bounds__(128)
amblock_kernel(const float* __restrict__ x,
               const float* __restrict__ hk,
               float* __restrict__ out)
{
    __shared__ float s_w[48 * 16];
    __shared__ float s_feat[8][49];   // 48 feats + 1 pad

    const int tid = threadIdx.x;

    // stage weights (reused by every block; L2-hot)
#pragma unroll
    for (int i = tid; i < 768; i += 128) s_w[i] = hk[i];

    const int c  = tid & 15;
    const int px = tid >> 4;                 // 0..7
    const int w0 = blockIdx.x * 8 + px;
    const int h0 = blockIdx.y;
    const int b0 = blockIdx.z;

    const float* xb = x + ((size_t)b0 * HH * WW * CC) + c;

    // clamped row/col indices + validity masks for zero padding
    int  hcl[7], wcl[7];
    bool rok[7], cok[7];
#pragma unroll
    for (int r = 0; r < 7; r++) {
        int hh = h0 + r - 3;
        rok[r] = (hh >= 0) && (hh < HH);
        hcl[r] = hh < 0 ? 0 : (hh > HH - 1 ? HH - 1 : hh);
        int ww = w0 + r - 3;
        cok[r] = (ww >= 0) && (ww < WW);
        wcl[r] = ww < 0 ? 0 : (ww > WW - 1 ? WW - 1 : ww);
    }

    float win[49];
#pragma unroll
    for (int r = 0; r < 7; r++) {
        const float* rowp = xb + (size_t)hcl[r] * (WW * CC);
#pragma unroll
        for (int q = 0; q < 7; q++) {
            float t = rowp[wcl[q] * CC];
            win[r * 7 + q] = (rok[r] && cok[q]) ? t : 0.0f;
        }
    }

    // k=3 window: rows/cols 2..4 of the 7x7; rank index 6 of 9
    float v3[9];
#pragma unroll
    for (int r = 0; r < 3; r++)
#pragma unroll
        for (int q = 0; q < 3; q++)
            v3[r * 3 + q] = win[(r + 2) * 7 + (q + 2)];
    const float m3 = rank_select<9, 6>(v3);

    // k=5 window: rows/cols 1..5; rank index 14 of 25
    float v5[25];
#pragma unroll
    for (int r = 0; r < 5; r++)
#pragma unroll
        for (int q = 0; q < 5; q++)
            v5[r * 5 + q] = win[(r + 1) * 7 + (q + 1)];
    const float m5 = rank_select<25, 14>(v5);

    // k=7: whole window (destroyed in place); rank index 26 of 49
    const float m7 = rank_select<49, 26>(win);

    // feature order matches reference concat: [m7, m3, m5]
    s_feat[px][c]      = m7;
    s_feat[px][16 + c] = m3;
    s_feat[px][32 + c] = m5;
    __syncthreads();

    // 1x1 conv: thread (px, o=c) -> out[b,h,w,o]
    float acc = 0.0f;
#pragma unroll
    for (int j = 0; j < 48; j++)
        acc = fmaf(s_feat[px][j], s_w[j * 16 + c], acc);

    out[(((size_t)b0 * HH + h0) * WW + w0) * CC + c] = acc;
}

extern "C" void kernel_launch(void* const* d_in, const int* in_sizes, int n_in,
                              void* d_out, int out_size)
{
    const float* x  = (const float*)d_in[0];   // [4,256,256,16]
    const float* hk = (const float*)d_in[1];   // [1,1,48,16] -> 768 floats
    float* out = (float*)d_out;                // [4,256,256,16]

    dim3 grid(WW / 8, HH, BB);
    dim3 block(128);
    amblock_kernel<<<grid, block>>>(x, hk, out);
}

// round 8
// speedup vs baseline: 1.6527x; 1.6527x over previous
#include <cuda_runtime.h>

#define BB 4
#define HH 256
#define WW 256
#define CC 16

// ---------------------------------------------------------------------------
// Compile-time comparator-network generator.
//
// ONE incremental network over the 49 window values instead of three
// independent sorts:
//     s9  = sort(inner 3x3)            -> rank 6  = m3   (snapshot at c1)
//     s16 = sort(5x5 ring)
//     s25 = merge(s9, s16)             -> rank 14 = m5   (snapshot at c2)
//     s24 = sort(7x7 ring)
//     s49 = merge(s25, s24)            -> rank 26 = m7   (end)
// CRITICAL: later merges REUSE the wires of earlier sorted runs, so the m3
// and m5 values must be snapshotted at their checkpoints, not read at the
// end (that was Round 6's bug: end-reads saw clobbered wires).
// Sorts/merges are Batcher odd-even (arbitrary length, recursive, wire-
// position tracked). Only three snapshots are consumed, so nvcc DCE prunes
// every compare-exchange outside their dependency cones.
// ---------------------------------------------------------------------------
struct Net {
    int n;
    unsigned char ia[768];
    unsigned char ib[768];
};

struct IdxList {
    int n;
    unsigned char v[64];
};

// Batcher odd-even merge of two sorted runs (arbitrary lengths).
// CE semantics at runtime: v[ia] = min, v[ib] = max.
__host__ __device__ constexpr IdxList oem(const IdxList& A, const IdxList& B, Net& net) {
    IdxList R{};
    if (A.n == 0) return B;
    if (B.n == 0) return A;
    if (A.n == 1 && B.n == 1) {
        net.ia[net.n] = A.v[0];
        net.ib[net.n] = B.v[0];
        net.n++;
        R.n = 2; R.v[0] = A.v[0]; R.v[1] = B.v[0];
        return R;
    }
    IdxList Ao{}, Ae{}, Bo{}, Be{};
    for (int i = 0; i < A.n; i++) {
        if ((i & 1) == 0) Ao.v[Ao.n++] = A.v[i];
        else              Ae.v[Ae.n++] = A.v[i];
    }
    for (int i = 0; i < B.n; i++) {
        if ((i & 1) == 0) Bo.v[Bo.n++] = B.v[i];
        else              Be.v[Be.n++] = B.v[i];
    }
    IdxList O = oem(Ao, Bo, net);
    IdxList E = oem(Ae, Be, net);
    R.v[R.n++] = O.v[0];
    int ei = 0, oi = 1;
    while (ei < E.n && oi < O.n) {
        net.ia[net.n] = E.v[ei];
        net.ib[net.n] = O.v[oi];
        net.n++;
        R.v[R.n++] = E.v[ei];
        R.v[R.n++] = O.v[oi];
        ei++; oi++;
    }
    while (ei < E.n) R.v[R.n++] = E.v[ei++];
    while (oi < O.n) R.v[R.n++] = O.v[oi++];
    return R;
}

__host__ __device__ constexpr IdxList msort(const IdxList& L, Net& net) {
    if (L.n <= 1) return L;
    IdxList A{}, B{};
    const int h = L.n / 2;
    for (int i = 0; i < h; i++)    A.v[A.n++] = L.v[i];
    for (int i = h; i < L.n; i++)  B.v[B.n++] = L.v[i];
    IdxList As = msort(A, net);
    IdxList Bs = msort(B, net);
    return oem(As, Bs, net);
}

struct Plan {
    Net net;
    int c1, c2;       // comparator-count checkpoints
    int p3, p5, p7;   // wire positions valid AT their checkpoints
};

__host__ __device__ constexpr Plan make_plan() {
    Plan P{};
    IdxList i3{}, r5{}, r7{};
    for (int r = 0; r < 7; r++)
        for (int q = 0; q < 7; q++) {
            const int idx = r * 7 + q;
            const bool in3 = (r >= 2 && r <= 4 && q >= 2 && q <= 4);
            const bool in5 = (r >= 1 && r <= 5 && q >= 1 && q <= 5);
            if (in3)      i3.v[i3.n++] = (unsigned char)idx;
            else if (in5) r5.v[r5.n++] = (unsigned char)idx;
            else          r7.v[r7.n++] = (unsigned char)idx;
        }
    IdxList s9  = msort(i3, P.net);
    P.p3 = s9.v[6];                       // n=9,  m=3  -> ascending idx 6
    P.c1 = P.net.n;                       // m3 valid here
    IdxList s16 = msort(r5, P.net);
    IdxList s25 = oem(s9, s16, P.net);
    P.p5 = s25.v[14];                     // n=25, m=11 -> ascending idx 14
    P.c2 = P.net.n;                       // m5 valid here
    IdxList s24 = msort(r7, P.net);
    IdxList s49 = oem(s25, s24, P.net);
    P.p7 = s49.v[26];                     // n=49, m=23 -> ascending idx 26
    return P;
}

// One network segment [t0, t1). Every 4th comparator uses arithmetic min/max
// on the fma pipe to break the single-pipe FMNMX ceiling (alu rt=2, fma rt=2
// per SMSP; a 3:1 mix raises sustainable CE throughput from 1/4cyc to 1/3cyc).
template <int SEG>
__device__ __forceinline__ void run_segment(float (&win)[49], int t0, int t1) {
    constexpr Plan P = make_plan();
#pragma unroll
    for (int t = 0; t < P.net.n; t++) {
        if (t < t0 || t >= t1) continue;
        const int a = P.net.ia[t];
        const int b = P.net.ib[t];
        float xv = win[a];
        float yv = win[b];
        if ((t & 3) == 0) {
            float s = xv + yv;
            float d = fabsf(xv - yv);
            win[a] = 0.5f * (s - d);
            win[b] = 0.5f * (s + d);
        } else {
            win[a] = fminf(xv, yv);
            win[b] = fmaxf(xv, yv);
        }
    }
}

// ---------------------------------------------------------------------------
// Block: 128 threads = 8 pixels x 16 channels. Interior blocks take a
// select-free gather; boundary blocks take the clamped+masked path. One
// combined selection network with checkpointed snapshots, smem feature
// exchange, and the 48x16 1x1-conv mix with coalesced stores.
// ---------------------------------------------------------------------------
__global__ void __launch_bounds__(128)
amblock_kernel(const float* __restrict__ x,
               const float* __restrict__ hk,
               float* __restrict__ out)
{
    __shared__ float s_w[48 * 16];
    __shared__ float s_feat[8][49];

    const int tid = threadIdx.x;

#pragma unroll
    for (int i = tid; i < 768; i += 128) s_w[i] = hk[i];

    const int c  = tid & 15;
    const int px = tid >> 4;
    const int w0 = blockIdx.x * 8 + px;
    const int h0 = blockIdx.y;
    const int b0 = blockIdx.z;

    const float* xb = x + ((size_t)b0 * HH * WW * CC) + c;

    float win[49];

    const bool interior = (h0 >= 3) && (h0 <= HH - 4) &&
                          (blockIdx.x > 0) && (blockIdx.x < (WW / 8) - 1);

    if (interior) {
        const float* p0 = xb + (size_t)(h0 - 3) * (WW * CC) + (w0 - 3) * CC;
#pragma unroll
        for (int r = 0; r < 7; r++)
#pragma unroll
            for (int q = 0; q < 7; q++)
                win[r * 7 + q] = p0[(size_t)r * (WW * CC) + q * CC];
    } else {
        int  hcl[7], wcl[7];
        bool rok[7], cok[7];
#pragma unroll
        for (int r = 0; r < 7; r++) {
            int hh = h0 + r - 3;
            rok[r] = (hh >= 0) && (hh < HH);
            hcl[r] = hh < 0 ? 0 : (hh > HH - 1 ? HH - 1 : hh);
            int ww = w0 + r - 3;
            cok[r] = (ww >= 0) && (ww < WW);
            wcl[r] = ww < 0 ? 0 : (ww > WW - 1 ? WW - 1 : ww);
        }
#pragma unroll
        for (int r = 0; r < 7; r++) {
            const float* rowp = xb + (size_t)hcl[r] * (WW * CC);
#pragma unroll
            for (int q = 0; q < 7; q++) {
                float t = rowp[wcl[q] * CC];
                win[r * 7 + q] = (rok[r] && cok[q]) ? t : 0.0f;
            }
        }
    }

    constexpr Plan P = make_plan();

    // Segment 1: sort of inner 3x3 -> snapshot m3 (wires later clobbered).
    run_segment<0>(win, 0, P.c1);
    const float m3 = win[P.p3];

    // Segment 2: sort ring16 + merge to sorted25 -> snapshot m5.
    run_segment<1>(win, P.c1, P.c2);
    const float m5 = win[P.p5];

    // Segment 3: sort ring24 + merge to sorted49 -> m7.
    run_segment<2>(win, P.c2, P.net.n);
    const float m7 = win[P.p7];

    // feature order matches reference concat: [m7, m3, m5]
    s_feat[px][c]      = m7;
    s_feat[px][16 + c] = m3;
    s_feat[px][32 + c] = m5;
    __syncthreads();

    float acc = 0.0f;
#pragma unroll
    for (int j = 0; j < 48; j++)
        acc = fmaf(s_feat[px][j], s_w[j * 16 + c], acc);

    out[(((size_t)b0 * HH + h0) * WW + w0) * CC + c] = acc;
}

extern "C" void kernel_launch(void* const* d_in, const int* in_sizes, int n_in,
                              void* d_out, int out_size)
{
    const float* x  = (const float*)d_in[0];   // [4,256,256,16]
    const float* hk = (const float*)d_in[1];   // [1,1,48,16] -> 768 floats
    float* out = (float*)d_out;                // [4,256,256,16]

    dim3 grid(WW / 8, HH, BB);
    dim3 block(128);
    amblock_kernel<<<grid, block>>>(x, hk, out);
}